// round 11
// baseline (speedup 1.0000x reference)
#include <cuda_runtime.h>
#include <cuda_fp16.h>
#include <cstddef>

// Problem constants (match reference_code)
#define T_STEPS 600
#define N_REC   5000
#define N_IN    100
#define N_OUT   100
#define NR4     1250            // N_REC / 4
#define KPAD    5120            // padded columns (20 groups of 256)
#define NWU4    640             // uint4 words per fp16 row (KPAD/8)
#define NH2W    2560            // half2 words per fp16 row
#define P_PIN   20              // fp16 rows pinned in SMEM per block (even!)
#define PTHREADS 768
#define NWARPS  24

// smem: rs [0,20480) | Wpin [20480,225280)
#define SM_TOTAL_BYTES 225280

// Scratch (allocation-free rule: __device__ globals)
__device__ float    g_x[N_REC];
__device__ float    g_drive[(size_t)T_STEPS * N_REC];
__device__ unsigned g_bar;
__device__ __align__(16) unsigned g_w16[(size_t)N_REC * NH2W]; // 51.2 MB fp16 W

__device__ __forceinline__ unsigned ld_acq(const unsigned* p) {
    unsigned v;
    asm volatile("ld.global.acquire.gpu.u32 %0, [%1];" : "=r"(v) : "l"(p));
    return v;
}
__device__ __forceinline__ float warp_reduce(float s) {
    #pragma unroll
    for (int o = 16; o; o >>= 1) s += __shfl_xor_sync(0xffffffffu, s, o);
    return s;
}

// ---------------------------------------------------------------------------
// init: hidden[0] = r, x = arctanh(r), reset grid barrier
// ---------------------------------------------------------------------------
__global__ void init_kernel(const float* __restrict__ r, float* __restrict__ hidden) {
    int i = blockIdx.x * blockDim.x + threadIdx.x;
    if (i == 0) g_bar = 0u;
    if (i < N_REC) {
        float rv = r[i];
        hidden[i] = rv;
        g_x[i] = atanhf(rv);
    }
}

// ---------------------------------------------------------------------------
// convert ALL W rows to fp16, (c, c+32)-pair interleaved uint4 layout:
//   half2 word w of a row: i=w>>2 (uint4 idx), k=w&3, jp=i>>5, l=i&31
//   -> cols c1 = 256*jp + 64*k + l, c2 = c1 + 32   (0 if col >= 5000)
// ---------------------------------------------------------------------------
__global__ __launch_bounds__(256) void conv_kernel(const float* __restrict__ W) {
    size_t e = (size_t)blockIdx.x * blockDim.x + threadIdx.x;
    if (e >= (size_t)N_REC * NH2W) return;
    int row = (int)(e / NH2W);
    int w   = (int)(e % NH2W);
    int i = w >> 2, k = w & 3;
    int jp = i >> 5, l = i & 31;
    int c1 = (jp << 8) + (k << 6) + l;
    int c2 = c1 + 32;
    const float* src = W + (size_t)row * N_REC;
    float a = (c1 < N_REC) ? src[c1] : 0.0f;
    float b = (c2 < N_REC) ? src[c2] : 0.0f;
    __half2 h = __floats2half2_rn(a, b);
    g_w16[e] = *(unsigned*)&h;
}

// ---------------------------------------------------------------------------
// drive[t][i] = sum_k u[t][k] * W_in[i][k] + eps[t][i]
// ---------------------------------------------------------------------------
#define DRIVE_TT 25
__global__ __launch_bounds__(128) void drive_kernel(
    const float* __restrict__ u, const float* __restrict__ W_in,
    const float* __restrict__ eps)
{
    __shared__ float us[DRIVE_TT][N_IN];
    int i  = blockIdx.x * 128 + threadIdx.x;
    int t0 = blockIdx.y * DRIVE_TT;

    for (int idx = threadIdx.x; idx < DRIVE_TT * N_IN; idx += 128) {
        int tl = idx / N_IN, k = idx % N_IN;
        us[tl][k] = u[(size_t)(t0 + tl) * N_IN + k];
    }
    __syncthreads();
    if (i >= N_REC) return;

    const float* __restrict__ Wr = W_in + (size_t)i * N_IN;
    for (int tl = 0; tl < DRIVE_TT; ++tl) {
        float acc = 0.0f;
        #pragma unroll 4
        for (int k = 0; k < N_IN; ++k)
            acc += __ldg(Wr + k) * us[tl][k];
        int t = t0 + tl;
        g_drive[(size_t)t * N_REC + i] = acc + eps[(size_t)t * N_REC + i];
    }
}

// pair dot: two full fp16 rows against rs; each rs value loaded ONCE.
// GLB=true -> W rows from global (L2-resident), else from SMEM.
template <bool GLB>
__device__ __forceinline__ void pair_dot(const uint4* __restrict__ Wa,
                                         const uint4* __restrict__ Wb,
                                         const float* __restrict__ rs,
                                         int lane, float& sa, float& sb)
{
    float a0 = 0.f, a1 = 0.f, b0 = 0.f, b1 = 0.f;
    #pragma unroll 4
    for (int jp = 0; jp < 20; ++jp) {
        uint4 qa = GLB ? __ldg(Wa + (jp << 5) + lane) : Wa[(jp << 5) + lane];
        uint4 qb = GLB ? __ldg(Wb + (jp << 5) + lane) : Wb[(jp << 5) + lane];
        int cb = (jp << 8) + lane;
        float r0 = rs[cb],       r1 = rs[cb + 32],
              r2 = rs[cb + 64],  r3 = rs[cb + 96],
              r4 = rs[cb + 128], r5 = rs[cb + 160],
              r6 = rs[cb + 192], r7 = rs[cb + 224];
        float2 fa0 = __half22float2(*reinterpret_cast<const __half2*>(&qa.x));
        float2 fa1 = __half22float2(*reinterpret_cast<const __half2*>(&qa.y));
        float2 fa2 = __half22float2(*reinterpret_cast<const __half2*>(&qa.z));
        float2 fa3 = __half22float2(*reinterpret_cast<const __half2*>(&qa.w));
        float2 fb0 = __half22float2(*reinterpret_cast<const __half2*>(&qb.x));
        float2 fb1 = __half22float2(*reinterpret_cast<const __half2*>(&qb.y));
        float2 fb2 = __half22float2(*reinterpret_cast<const __half2*>(&qb.z));
        float2 fb3 = __half22float2(*reinterpret_cast<const __half2*>(&qb.w));
        a0 += fa0.x * r0 + fa0.y * r1;
        a1 += fa1.x * r2 + fa1.y * r3;
        a0 += fa2.x * r4 + fa2.y * r5;
        a1 += fa3.x * r6 + fa3.y * r7;
        b0 += fb0.x * r0 + fb0.y * r1;
        b1 += fb1.x * r2 + fb1.y * r3;
        b0 += fb2.x * r4 + fb2.y * r5;
        b1 += fb3.x * r6 + fb3.y * r7;
    }
    sa = a0 + a1;
    sb = b0 + b1;
}

// ---------------------------------------------------------------------------
// Persistent RNN rollout, warp-per-row-pair.
//   - block owns ~34 contiguous rows; first 20 pinned in SMEM (fp16),
//     rest streamed via __ldg from L2 (20.9 MB/step chip-wide, resident).
//   - 17 pair tasks over 24 warps; lane 0 updates both rows directly
//     (no partial-sum smem, no combine sync): 3 syncs/step total.
//   - 225 KB smem -> occupancy 1; grid == #SMs -> barrier is safe.
// ---------------------------------------------------------------------------
__global__ __launch_bounds__(PTHREADS, 1) void rnn_persistent(
    float* __restrict__ hidden, int G)
{
    extern __shared__ float sm[];
    float* rs   = sm;                                  // [KPAD]
    uint4* Wpin = (uint4*)(sm + KPAD);                 // [P_PIN * NWU4]

    const int b    = blockIdx.x;
    const int tid  = threadIdx.x;
    const int warp = tid >> 5;
    const int lane = tid & 31;

    // contiguous row range for this block
    const int base = N_REC / G, rem = N_REC % G;
    const int nrows  = base + (b < rem ? 1 : 0);
    const int rstart = b * base + (b < rem ? b : rem);
    const int npairs = (nrows + 1) >> 1;

    // zero rs padding (cols 5000..5119); stage loop never writes there
    if (tid < KPAD - N_REC) rs[N_REC + tid] = 0.0f;

    // pin first P_PIN rows (contiguous in g_w16)
    {
        const uint4* src = (const uint4*)g_w16 + (size_t)rstart * NWU4;
        for (int i = tid; i < P_PIN * NWU4; i += PTHREADS) Wpin[i] = src[i];
    }

    const uint4* gW = (const uint4*)g_w16;

    for (int t = 0; t < T_STEPS; ++t) {
        // stage r_prev = hidden[t] (1250 float4)
        {
            const float4* rg = (const float4*)(hidden + (size_t)t * N_REC);
            float4* rd = (float4*)rs;
            for (int i = tid; i < NR4; i += PTHREADS) rd[i] = rg[i];
        }
        __syncthreads();

        // pair tasks: rows (2p, 2p+1)
        for (int p = warp; p < npairs; p += NWARPS) {
            int ra = 2 * p;
            int rb = 2 * p + 1;
            bool hasb = (rb < nrows);
            float sa, sb;
            if (ra < P_PIN) {   // P_PIN even => rb also pinned
                pair_dot<false>(Wpin + (size_t)ra * NWU4,
                                Wpin + (size_t)rb * NWU4, rs, lane, sa, sb);
            } else {
                const uint4* Wa = gW + (size_t)(rstart + ra) * NWU4;
                const uint4* Wb = gW + (size_t)(rstart + (hasb ? rb : ra)) * NWU4;
                pair_dot<true>(Wa, Wb, rs, lane, sa, sb);
            }
            sa = warp_reduce(sa);
            sb = warp_reduce(sb);
            if (lane == 0) {
                int rowa = rstart + ra;
                float xa = g_x[rowa];
                xa = 0.9f * xa + 0.1f * (sa + g_drive[(size_t)t * N_REC + rowa]);
                g_x[rowa] = xa;
                hidden[(size_t)(t + 1) * N_REC + rowa] = tanhf(xa);
                if (hasb) {
                    int rowb = rstart + rb;
                    float xb = g_x[rowb];
                    xb = 0.9f * xb + 0.1f * (sb + g_drive[(size_t)t * N_REC + rowb]);
                    g_x[rowb] = xb;
                    hidden[(size_t)(t + 1) * N_REC + rowb] = tanhf(xb);
                }
            }
        }
        __syncthreads();

        // grid barrier
        if (tid == 0) {
            __threadfence();
            atomicAdd(&g_bar, 1u);
            unsigned tgt = (unsigned)G * (unsigned)(t + 1);
            while (ld_acq(&g_bar) < tgt) __nanosleep(64);
        }
        __syncthreads();
    }
}

// ---------------------------------------------------------------------------
// out: o[t][j] = sum_i hidden[t+1][i] * W_out[j][i]
// ---------------------------------------------------------------------------
#define OUT_OT 2
__global__ __launch_bounds__(512) void out_kernel(
    const float* __restrict__ hidden, const float* __restrict__ W_out,
    float* __restrict__ o)
{
    __shared__ float4 rsh[OUT_OT][NR4];
    int tid = threadIdx.x;
    int t0  = blockIdx.x * OUT_OT;

    for (int i = tid; i < OUT_OT * NR4; i += 512) {
        int tl = i / NR4, v = i % NR4;
        rsh[tl][v] = ((const float4*)(hidden + (size_t)(t0 + tl + 1) * N_REC))[v];
    }
    __syncthreads();

    int w    = tid >> 5;
    int lane = tid & 31;

    for (int task = w; task < N_OUT * OUT_OT; task += 16) {
        int j  = task >> 1;
        int tl = task & 1;
        const float4* __restrict__ Wr = (const float4*)(W_out + (size_t)j * N_REC);
        const float4* __restrict__ rr = rsh[tl];

        float4 a = make_float4(0.f, 0.f, 0.f, 0.f);
        #pragma unroll 8
        for (int v = lane; v < NR4; v += 32) {
            float4 wv = __ldg(Wr + v);
            float4 rv = rr[v];
            a.x += wv.x * rv.x;
            a.y += wv.y * rv.y;
            a.z += wv.z * rv.z;
            a.w += wv.w * rv.w;
        }
        float s = warp_reduce((a.x + a.y) + (a.z + a.w));
        if (lane == 0) o[(size_t)(t0 + tl) * N_OUT + j] = s;
    }
}

// ---------------------------------------------------------------------------
// kernel_launch (graph-capturable, allocation-free)
// Inputs: 0:u [600,100] 1:r [5000] 2:W_in [5000,100] 3:W_rec [5000,5000]
//         4:W_out [100,5000] 5:eps [600,5000]
// Output: hidden_states [601,5000] then o [600,100]
// ---------------------------------------------------------------------------
extern "C" void kernel_launch(void* const* d_in, const int* in_sizes, int n_in,
                              void* d_out, int out_size)
{
    const float* u     = (const float*)d_in[0];
    const float* r     = (const float*)d_in[1];
    const float* W_in  = (const float*)d_in[2];
    const float* W_rec = (const float*)d_in[3];
    const float* W_out = (const float*)d_in[4];
    const float* eps   = (const float*)d_in[5];

    float* hidden = (float*)d_out;                          // [601, 5000]
    float* o      = hidden + (size_t)(T_STEPS + 1) * N_REC; // [600, 100]

    int dev = 0, sms = 148;
    cudaGetDevice(&dev);
    cudaDeviceGetAttribute(&sms, cudaDevAttrMultiProcessorCount, dev);
    int G = sms;
    if (G < 1) G = 1;

    cudaFuncSetAttribute(rnn_persistent,
                         cudaFuncAttributeMaxDynamicSharedMemorySize, SM_TOTAL_BYTES);

    init_kernel<<<(N_REC + 255) / 256, 256>>>(r, hidden);

    const size_t conv_total = (size_t)N_REC * NH2W;
    conv_kernel<<<(unsigned)((conv_total + 255) / 256), 256>>>(W_rec);

    dim3 dgrid((N_REC + 127) / 128, T_STEPS / DRIVE_TT);
    drive_kernel<<<dgrid, 128>>>(u, W_in, eps);

    rnn_persistent<<<G, PTHREADS, SM_TOTAL_BYTES>>>(hidden, G);

    out_kernel<<<T_STEPS / OUT_OT, 512>>>(hidden, W_out, o);
}

// round 12
// speedup vs baseline: 1.1369x; 1.1369x over previous
#include <cuda_runtime.h>
#include <cuda_fp16.h>
#include <cstddef>

// Problem constants (match reference_code)
#define T_STEPS 600
#define N_REC   5000
#define N_IN    100
#define N_OUT   100
#define NR4     1250            // N_REC / 4
#define KPAD    5120            // padded columns (20 groups of 256)
#define NWU4    640             // uint4 words per fp16 row (KPAD/8)
#define NH2W    2560            // half2 words per fp16 row
#define P_PIN   20              // fp16 rows pinned in SMEM per block
#define PTHREADS 1024
#define NWARPS  32

// smem floats: rs [0,5120) | Wpin [5120,56320) | part [56320,56456)
#define SM_TOTAL_BYTES 225824

// Scratch (allocation-free rule: __device__ globals)
__device__ float    g_x[N_REC];
__device__ float    g_drive[(size_t)T_STEPS * N_REC];
__device__ unsigned g_bar;
__device__ __align__(16) unsigned g_w16[(size_t)N_REC * NH2W]; // 51.2 MB fp16 W

__device__ __forceinline__ unsigned ld_acq(const unsigned* p) {
    unsigned v;
    asm volatile("ld.global.acquire.gpu.u32 %0, [%1];" : "=r"(v) : "l"(p));
    return v;
}
__device__ __forceinline__ float warp_reduce(float s) {
    #pragma unroll
    for (int o = 16; o; o >>= 1) s += __shfl_xor_sync(0xffffffffu, s, o);
    return s;
}

// ---------------------------------------------------------------------------
// init: hidden[0] = r, x = arctanh(r), reset grid barrier
// ---------------------------------------------------------------------------
__global__ void init_kernel(const float* __restrict__ r, float* __restrict__ hidden) {
    int i = blockIdx.x * blockDim.x + threadIdx.x;
    if (i == 0) g_bar = 0u;
    if (i < N_REC) {
        float rv = r[i];
        hidden[i] = rv;
        g_x[i] = atanhf(rv);
    }
}

// ---------------------------------------------------------------------------
// convert ALL W rows to fp16, (c, c+32)-pair interleaved uint4 layout:
//   half2 word w of a row: i=w>>2 (uint4 idx), k=w&3, jp=i>>5, l=i&31
//   -> cols c1 = 256*jp + 64*k + l, c2 = c1 + 32   (0 if col >= 5000)
// ---------------------------------------------------------------------------
__global__ __launch_bounds__(256) void conv_kernel(const float* __restrict__ W) {
    size_t e = (size_t)blockIdx.x * blockDim.x + threadIdx.x;
    if (e >= (size_t)N_REC * NH2W) return;
    int row = (int)(e / NH2W);
    int w   = (int)(e % NH2W);
    int i = w >> 2, k = w & 3;
    int jp = i >> 5, l = i & 31;
    int c1 = (jp << 8) + (k << 6) + l;
    int c2 = c1 + 32;
    const float* src = W + (size_t)row * N_REC;
    float a = (c1 < N_REC) ? src[c1] : 0.0f;
    float b = (c2 < N_REC) ? src[c2] : 0.0f;
    __half2 h = __floats2half2_rn(a, b);
    g_w16[e] = *(unsigned*)&h;
}

// ---------------------------------------------------------------------------
// drive[t][i] = sum_k u[t][k] * W_in[i][k] + eps[t][i]
// ---------------------------------------------------------------------------
#define DRIVE_TT 25
__global__ __launch_bounds__(128) void drive_kernel(
    const float* __restrict__ u, const float* __restrict__ W_in,
    const float* __restrict__ eps)
{
    __shared__ float us[DRIVE_TT][N_IN];
    int i  = blockIdx.x * 128 + threadIdx.x;
    int t0 = blockIdx.y * DRIVE_TT;

    for (int idx = threadIdx.x; idx < DRIVE_TT * N_IN; idx += 128) {
        int tl = idx / N_IN, k = idx % N_IN;
        us[tl][k] = u[(size_t)(t0 + tl) * N_IN + k];
    }
    __syncthreads();
    if (i >= N_REC) return;

    const float* __restrict__ Wr = W_in + (size_t)i * N_IN;
    for (int tl = 0; tl < DRIVE_TT; ++tl) {
        float acc = 0.0f;
        #pragma unroll 4
        for (int k = 0; k < N_IN; ++k)
            acc += __ldg(Wr + k) * us[tl][k];
        int t = t0 + tl;
        g_drive[(size_t)t * N_REC + i] = acc + eps[(size_t)t * N_REC + i];
    }
}

// quarter-row dot: jp groups [q*5, q*5+5) of one fp16 row (1280 columns).
// GLB=true -> W from global (L2-resident), else from SMEM (conflict-free).
template <bool GLB>
__device__ __forceinline__ float quarter_dot(const uint4* __restrict__ Wr,
                                             const float* __restrict__ rs,
                                             int q, int lane)
{
    float a0 = 0.f, a1 = 0.f;
    #pragma unroll
    for (int jj = 0; jj < 5; ++jj) {
        int jp = q * 5 + jj;
        uint4 w = GLB ? __ldg(Wr + (jp << 5) + lane) : Wr[(jp << 5) + lane];
        int cb = (jp << 8) + lane;
        float2 f0 = __half22float2(*reinterpret_cast<const __half2*>(&w.x));
        float2 f1 = __half22float2(*reinterpret_cast<const __half2*>(&w.y));
        float2 f2 = __half22float2(*reinterpret_cast<const __half2*>(&w.z));
        float2 f3 = __half22float2(*reinterpret_cast<const __half2*>(&w.w));
        a0 += f0.x * rs[cb]       + f0.y * rs[cb + 32];
        a1 += f1.x * rs[cb + 64]  + f1.y * rs[cb + 96];
        a0 += f2.x * rs[cb + 128] + f2.y * rs[cb + 160];
        a1 += f3.x * rs[cb + 192] + f3.y * rs[cb + 224];
    }
    return a0 + a1;
}

// ---------------------------------------------------------------------------
// Persistent RNN rollout, warp-per-quarter-row, 32 warps.
//   - block owns ~34 contiguous rows; first 20 pinned in SMEM (fp16),
//     rest streamed via __ldg from L2 (20.9 MB/step chip-wide, resident).
//   - 4*nrows (~136) quarter tasks over 32 warps: path 25 iters, balanced.
//   - 4 syncs/step; 225.8 KB smem -> occupancy 1; grid == #SMs.
// ---------------------------------------------------------------------------
__global__ __launch_bounds__(PTHREADS, 1) void rnn_persistent(
    float* __restrict__ hidden, int G)
{
    extern __shared__ float sm[];
    float* rs   = sm;                                  // [KPAD]
    uint4* Wpin = (uint4*)(sm + KPAD);                 // [P_PIN * NWU4]
    float* part = sm + KPAD + P_PIN * NWU4 * 4;        // [4 * nrows]

    const int b    = blockIdx.x;
    const int tid  = threadIdx.x;
    const int warp = tid >> 5;
    const int lane = tid & 31;

    // contiguous row range for this block
    const int base = N_REC / G, rem = N_REC % G;
    const int nrows  = base + (b < rem ? 1 : 0);
    const int rstart = b * base + (b < rem ? b : rem);
    const int ntasks = 4 * nrows;

    // zero rs padding (cols 5000..5119); stage loop never writes there
    if (tid < KPAD - N_REC) rs[N_REC + tid] = 0.0f;

    // pin first P_PIN rows (contiguous in g_w16)
    {
        const uint4* src = (const uint4*)g_w16 + (size_t)rstart * NWU4;
        for (int i = tid; i < P_PIN * NWU4; i += PTHREADS) Wpin[i] = src[i];
    }

    const uint4* gW = (const uint4*)g_w16;

    for (int t = 0; t < T_STEPS; ++t) {
        // stage r_prev = hidden[t] (1250 float4)
        {
            const float4* rg = (const float4*)(hidden + (size_t)t * N_REC);
            float4* rd = (float4*)rs;
            for (int i = tid; i < NR4; i += PTHREADS) rd[i] = rg[i];
        }
        __syncthreads();

        // quarter-row tasks
        for (int tau = warp; tau < ntasks; tau += NWARPS) {
            int local = tau >> 2;
            int q     = tau & 3;
            float acc;
            if (local < P_PIN)
                acc = quarter_dot<false>(Wpin + (size_t)local * NWU4, rs, q, lane);
            else
                acc = quarter_dot<true>(gW + (size_t)(rstart + local) * NWU4, rs, q, lane);
            acc = warp_reduce(acc);
            if (lane == 0) part[tau] = acc;
        }
        __syncthreads();

        // combine quarters + state update (one thread per row)
        if (tid < nrows) {
            int row = rstart + tid;
            float y = (part[4 * tid] + part[4 * tid + 1]) +
                      (part[4 * tid + 2] + part[4 * tid + 3]);
            float x = g_x[row];
            x = 0.9f * x + 0.1f * (y + g_drive[(size_t)t * N_REC + row]);
            g_x[row] = x;
            hidden[(size_t)(t + 1) * N_REC + row] = tanhf(x);
        }
        __syncthreads();

        // grid barrier
        if (tid == 0) {
            __threadfence();
            atomicAdd(&g_bar, 1u);
            unsigned tgt = (unsigned)G * (unsigned)(t + 1);
            while (ld_acq(&g_bar) < tgt) __nanosleep(64);
        }
        __syncthreads();
    }
}

// ---------------------------------------------------------------------------
// out: o[t][j] = sum_i hidden[t+1][i] * W_out[j][i]
// ---------------------------------------------------------------------------
#define OUT_OT 2
__global__ __launch_bounds__(512) void out_kernel(
    const float* __restrict__ hidden, const float* __restrict__ W_out,
    float* __restrict__ o)
{
    __shared__ float4 rsh[OUT_OT][NR4];
    int tid = threadIdx.x;
    int t0  = blockIdx.x * OUT_OT;

    for (int i = tid; i < OUT_OT * NR4; i += 512) {
        int tl = i / NR4, v = i % NR4;
        rsh[tl][v] = ((const float4*)(hidden + (size_t)(t0 + tl + 1) * N_REC))[v];
    }
    __syncthreads();

    int w    = tid >> 5;
    int lane = tid & 31;

    for (int task = w; task < N_OUT * OUT_OT; task += 16) {
        int j  = task >> 1;
        int tl = task & 1;
        const float4* __restrict__ Wr = (const float4*)(W_out + (size_t)j * N_REC);
        const float4* __restrict__ rr = rsh[tl];

        float4 a = make_float4(0.f, 0.f, 0.f, 0.f);
        #pragma unroll 8
        for (int v = lane; v < NR4; v += 32) {
            float4 wv = __ldg(Wr + v);
            float4 rv = rr[v];
            a.x += wv.x * rv.x;
            a.y += wv.y * rv.y;
            a.z += wv.z * rv.z;
            a.w += wv.w * rv.w;
        }
        float s = warp_reduce((a.x + a.y) + (a.z + a.w));
        if (lane == 0) o[(size_t)(t0 + tl) * N_OUT + j] = s;
    }
}

// ---------------------------------------------------------------------------
// kernel_launch (graph-capturable, allocation-free)
// Inputs: 0:u [600,100] 1:r [5000] 2:W_in [5000,100] 3:W_rec [5000,5000]
//         4:W_out [100,5000] 5:eps [600,5000]
// Output: hidden_states [601,5000] then o [600,100]
// ---------------------------------------------------------------------------
extern "C" void kernel_launch(void* const* d_in, const int* in_sizes, int n_in,
                              void* d_out, int out_size)
{
    const float* u     = (const float*)d_in[0];
    const float* r     = (const float*)d_in[1];
    const float* W_in  = (const float*)d_in[2];
    const float* W_rec = (const float*)d_in[3];
    const float* W_out = (const float*)d_in[4];
    const float* eps   = (const float*)d_in[5];

    float* hidden = (float*)d_out;                          // [601, 5000]
    float* o      = hidden + (size_t)(T_STEPS + 1) * N_REC; // [600, 100]

    int dev = 0, sms = 148;
    cudaGetDevice(&dev);
    cudaDeviceGetAttribute(&sms, cudaDevAttrMultiProcessorCount, dev);
    int G = sms;
    if (G < 1) G = 1;

    cudaFuncSetAttribute(rnn_persistent,
                         cudaFuncAttributeMaxDynamicSharedMemorySize, SM_TOTAL_BYTES);

    init_kernel<<<(N_REC + 255) / 256, 256>>>(r, hidden);

    const size_t conv_total = (size_t)N_REC * NH2W;
    conv_kernel<<<(unsigned)((conv_total + 255) / 256), 256>>>(W_rec);

    dim3 dgrid((N_REC + 127) / 128, T_STEPS / DRIVE_TT);
    drive_kernel<<<dgrid, 128>>>(u, W_in, eps);

    rnn_persistent<<<G, PTHREADS, SM_TOTAL_BYTES>>>(hidden, G);

    out_kernel<<<T_STEPS / OUT_OT, 512>>>(hidden, W_out, o);
}